// round 5
// baseline (speedup 1.0000x reference)
#include <cuda_runtime.h>
#include <math.h>

#define D 128
#define HD 1024
#define H 8
#define NCIR 585
#define NDIS 88
#define ECC 20000
#define EDD 3000
#define NB 296
#define NWARP (NB * 8)
#define FULL 0xffffffffu

__device__ __align__(16) float g_scratch[1720000];
__device__ unsigned g_cnt = 0;
__device__ volatile unsigned g_sense = 0;

struct BP {
    const float *x, *mat;
    const int *edges;
    const float *gb1, *ab, *gb2, *cw, *cb;
    const float *asrc, *adst, *aedge, *awe;
    const float *gw1, *aw, *gw2;
    float *fea;
    int N, E;
    float *ew, *deg, *h, *f1, *h2, *an_src, *an_dst, *att, *cvec, *ewsum;
    float *vsrc, *vdst;
    int *cnt, *rowptr, *cursor, *eid;
};
struct Pair { BP b[2]; };

static inline int pad4(int n) { return (n + 3) & ~3; }

// ---------------- helpers ----------------
__device__ __forceinline__ float4 ld4(const float* p) { return *(const float4*)p; }
__device__ __forceinline__ float wsum(float v) {
    #pragma unroll
    for (int o = 16; o; o >>= 1) v += __shfl_xor_sync(FULL, v, o);
    return v;
}
__device__ __forceinline__ float wmax(float v) {
    #pragma unroll
    for (int o = 16; o; o >>= 1) v = fmaxf(v, __shfl_xor_sync(FULL, v, o));
    return v;
}

// ---------------- device-wide barrier ----------------
__device__ __forceinline__ void gsync(unsigned* s_sense) {
    __syncthreads();
    __threadfence();
    __syncthreads();
    if (threadIdx.x == 0) {
        unsigned ns = *s_sense ^ 1u;
        *s_sense = ns;
        if (atomicAdd(&g_cnt, 1u) == NB - 1) {
            g_cnt = 0;
            __threadfence();
            g_sense = ns;
        } else {
            while (g_sense != ns) __nanosleep(64);
        }
        __threadfence();
    }
    __syncthreads();
}

// ---------------- edge pass 1 ----------------
__device__ void edge1_branch(const BP& bp, int gid) {
    int Er = (bp.E + 31) & ~31;
    for (int e = gid; e < Er; e += NB * 256) {
        float w = 0.f;
        if (e < bp.E) {
            int s = bp.edges[e], d = bp.edges[bp.E + e];
            w = bp.mat[s * bp.N + d];
            bp.ew[e] = w;
            atomicAdd(bp.deg + d, w);
            atomicAdd(bp.cnt + d, 1);
        }
        float ws = w;
        #pragma unroll
        for (int o = 16; o; o >>= 1) ws += __shfl_down_sync(FULL, ws, o);
        if ((threadIdx.x & 31) == 0 && ws != 0.f) atomicAdd(bp.ewsum, ws);
    }
}

// ---------------- scan (one block per branch) ----------------
__device__ void scan_branch(const BP& bp, float* sbuf, int tid) {
    int* sc = (int*)sbuf;
    int base = tid * 4;
    int v[4]; int s = 0;
    #pragma unroll
    for (int q = 0; q < 4; q++) {
        v[q] = (base + q < bp.N) ? bp.cnt[base + q] : 0;
        s += v[q];
    }
    sc[tid] = s; __syncthreads();
    #pragma unroll
    for (int off = 1; off < 256; off <<= 1) {
        int t2 = (tid >= off) ? sc[tid - off] : 0;
        __syncthreads();
        sc[tid] += t2;
        __syncthreads();
    }
    int run = sc[tid] - s;
    #pragma unroll
    for (int q = 0; q < 4; q++) {
        run += v[q];
        if (base + q < bp.N) {
            bp.rowptr[base + q + 1] = run;
            bp.cursor[base + q] = run - v[q];
            bp.deg[base + q] = rsqrtf(bp.deg[base + q]);
        }
    }
    if (tid == 0) bp.rowptr[0] = 0;
    __syncthreads();
}

// ---------------- tiled GEMM: C = A[M,128] @ W[128,ncols] ----------------
__device__ void gemm_phase(float* sA, int tid,
                           const float* A0, const float* W0, float* C0, int M0,
                           const float* A1, const float* W1, float* C1, int M1,
                           int ncols) {
    int cbn = ncols >> 7;
    int t0 = ((M0 + 15) >> 4) * cbn;
    int t1 = ((M1 + 15) >> 4) * cbn;
    for (int t = blockIdx.x; t < t0 + t1; t += NB) {
        int br = t >= t0;
        int tt = br ? t - t0 : t;
        const float* A = br ? A1 : A0;
        const float* W = br ? W1 : W0;
        float* C = br ? C1 : C0;
        int M = br ? M1 : M0;
        int rb = (tt / cbn) << 4;
        int cb = (tt % cbn) << 7;
        #pragma unroll
        for (int q = 0; q < 8; q++) {
            int idx = q * 256 + tid;
            int r = idx >> 7, k = idx & 127;
            sA[idx] = (rb + r < M) ? A[(rb + r) * 128 + k] : 0.f;
        }
        __syncthreads();
        int col = cb + (tid & 127);
        int r0 = (tid >> 7) << 3;
        float acc[8] = {0.f, 0.f, 0.f, 0.f, 0.f, 0.f, 0.f, 0.f};
        #pragma unroll 4
        for (int k = 0; k < 128; k++) {
            float w = W[k * ncols + col];
            #pragma unroll
            for (int r = 0; r < 8; r++) acc[r] = fmaf(sA[(r0 + r) * 128 + k], w, acc[r]);
        }
        #pragma unroll
        for (int r = 0; r < 8; r++)
            if (rb + r0 + r < M) C[(rb + r0 + r) * ncols + col] = acc[r];
        __syncthreads();
    }
}

// ---------------- warp-per-node GCN gather ----------------
__device__ float4 gather_warp(const BP& bp, int d, int lane, const float* bias) {
    float dd = bp.deg[d];
    float4 hv = ld4(bp.h + d * D + lane * 4);
    float4 b4 = ld4(bias + lane * 4);
    float sl = dd * dd;
    float4 acc;
    acc.x = fmaf(hv.x, sl, b4.x); acc.y = fmaf(hv.y, sl, b4.y);
    acc.z = fmaf(hv.z, sl, b4.z); acc.w = fmaf(hv.w, sl, b4.w);
    int rp = bp.rowptr[d], re = bp.rowptr[d + 1];
    for (int base = rp; base < re; base += 32) {
        int c = base + lane;
        int s = d; float nrm = 0.f;
        if (c < re) {
            int e = bp.eid[c];
            s = bp.edges[e];
            nrm = bp.deg[s] * bp.ew[e] * dd;
        }
        int cnt = min(32, re - base);
        for (int t = 0; t < cnt; t++) {
            int ss = __shfl_sync(FULL, s, t);
            float nn = __shfl_sync(FULL, nrm, t);
            float4 v = ld4(bp.h + ss * D + lane * 4);
            acc.x = fmaf(v.x, nn, acc.x); acc.y = fmaf(v.y, nn, acc.y);
            acc.z = fmaf(v.z, nn, acc.z); acc.w = fmaf(v.w, nn, acc.w);
        }
    }
    acc.x = fmaxf(acc.x, 0.f); acc.y = fmaxf(acc.y, 0.f);
    acc.z = fmaxf(acc.z, 0.f); acc.w = fmaxf(acc.w, 0.f);
    return acc;
}

// ---------------- warp-per-node attention dots ----------------
__device__ void an_warp(const BP& bp, int n, int lane) {
    float4 f = ld4(bp.f1 + n * D + lane * 4);
    #pragma unroll
    for (int hh = 0; hh < H; hh++) {
        float4 a = ld4(bp.vsrc + hh * D + lane * 4);
        float4 b = ld4(bp.vdst + hh * D + lane * 4);
        float s1 = f.x * a.x + f.y * a.y + f.z * a.z + f.w * a.w;
        float s2 = f.x * b.x + f.y * b.y + f.z * b.z + f.w * b.w;
        s1 = wsum(s1); s2 = wsum(s2);
        if (lane == 0) { bp.an_src[n * H + hh] = s1; bp.an_dst[n * H + hh] = s2; }
    }
}

// ---------------- warp-per-node fused GAT ----------------
__device__ void gat_warp(const BP& bp, int d, int lane) {
    int rp = bp.rowptr[d];
    int deg = bp.rowptr[d + 1] - rp;
    int total = deg + 1;
    float meanw = bp.ewsum[0] / (float)bp.E;
    float ad[H], ch[H], m[H], den[H];
    #pragma unroll
    for (int hh = 0; hh < H; hh++) {
        ad[hh] = bp.an_dst[d * H + hh];
        ch[hh] = bp.cvec[hh];
        m[hh] = -INFINITY; den[hh] = 0.f;
    }
    // pass 1: online softmax stats
    for (int base = 0; base < total; base += 32) {
        int c = base + lane;
        bool valid = c < total;
        int s = d; float w = meanw;
        if (c < deg) { int e = bp.eid[rp + c]; s = bp.edges[e]; w = bp.ew[e]; }
        #pragma unroll
        for (int hh = 0; hh < H; hh++) {
            float l = bp.an_src[s * H + hh] + ad[hh] + w * ch[hh];
            l = (l >= 0.f) ? l : 0.2f * l;
            if (!valid) l = -INFINITY;
            float cm = wmax(l);
            float nm = fmaxf(m[hh], cm);
            float ex = valid ? __expf(l - nm) : 0.f;
            float ls = wsum(ex);
            den[hh] = den[hh] * __expf(m[hh] - nm) + ls;
            m[hh] = nm;
        }
    }
    float inv[H];
    #pragma unroll
    for (int hh = 0; hh < H; hh++) inv[hh] = 1.f / (den[hh] + 1e-16f);
    // pass 2: aggregate
    float4 acc = {0.f, 0.f, 0.f, 0.f};
    for (int base = 0; base < total; base += 32) {
        int c = base + lane;
        bool valid = c < total;
        int s = d; float w = meanw;
        if (c < deg) { int e = bp.eid[rp + c]; s = bp.edges[e]; w = bp.ew[e]; }
        float cf[H];
        #pragma unroll
        for (int hh = 0; hh < H; hh++) {
            float l = bp.an_src[s * H + hh] + ad[hh] + w * ch[hh];
            l = (l >= 0.f) ? l : 0.2f * l;
            cf[hh] = valid ? __expf(l - m[hh]) * inv[hh] : 0.f;
        }
        int cnt = min(32, total - base);
        for (int t = 0; t < cnt; t++) {
            int ss = __shfl_sync(FULL, s, t);
            const float4* hrow = (const float4*)(bp.h2 + ss * HD) + lane;
            #pragma unroll
            for (int hh = 0; hh < H; hh++) {
                float c_h = __shfl_sync(FULL, cf[hh], t);
                float4 v = hrow[hh * 32];
                acc.x = fmaf(v.x, c_h, acc.x); acc.y = fmaf(v.y, c_h, acc.y);
                acc.z = fmaf(v.z, c_h, acc.z); acc.w = fmaf(v.w, c_h, acc.w);
            }
        }
    }
    float4 b4 = ld4(bp.ab + lane * 4);
    float4 o;
    o.x = fmaxf(fmaf(acc.x, 0.125f, b4.x), 0.f);
    o.y = fmaxf(fmaf(acc.y, 0.125f, b4.y), 0.f);
    o.z = fmaxf(fmaf(acc.z, 0.125f, b4.z), 0.f);
    o.w = fmaxf(fmaf(acc.w, 0.125f, b4.w), 0.f);
    *(float4*)(bp.att + d * D + lane * 4) = o;
}

// ---------------- phase A extras: va vectors + cvec ----------------
__device__ void prep_warp(const Pair& P, int tt, int lane) {
    if (tt < 4096) {
        int br = tt >> 11; int r = tt & 2047;
        int type = r >> 10; r &= 1023;
        int hh = r >> 7; int k = r & 127;
        const BP& bp = P.b[br];
        const float* avec = type ? bp.adst : bp.asrc;
        float* vout = type ? bp.vdst : bp.vsrc;
        float4 w4 = ld4(bp.aw + k * HD + hh * D + lane * 4);
        float4 a4 = ld4(avec + hh * D + lane * 4);
        float s = w4.x * a4.x + w4.y * a4.y + w4.z * a4.z + w4.w * a4.w;
        s = wsum(s);
        if (lane == 0) vout[hh * D + k] = s;
    } else {
        int r = tt - 4096;
        if (r >= 16) return;
        int br = r >> 3; int hh = r & 7;
        const BP& bp = P.b[br];
        float4 a = ld4(bp.awe + hh * D + lane * 4);
        float4 e = ld4(bp.aedge + hh * D + lane * 4);
        float s = a.x * e.x + a.y * e.y + a.z * e.z + a.w * e.w;
        s = wsum(s);
        if (lane == 0) bp.cvec[hh] = s;
    }
}

// ---------------- merged GCN2-gather + CNN head ----------------
__device__ void gather2_cnn_phase(const Pair& P, float* sA, int tid) {
    int wid = tid >> 5, lane = tid & 31;
    int g0 = (P.b[0].N + 15) >> 4;
    int g1 = (P.b[1].N + 15) >> 4;
    for (int t = blockIdx.x; t < g0 + g1; t += NB) {
        int br = t >= g0;
        const BP& bp = P.b[br];
        int rb = (br ? t - g0 : t) << 4;
        // warp wid gathers rows rb+2*wid, rb+2*wid+1 -> smem [f1 | f2]
        #pragma unroll
        for (int q = 0; q < 2; q++) {
            int r = 2 * wid + q;
            int d = rb + r;
            float4 f2v = {0.f, 0.f, 0.f, 0.f};
            float4 f1v = {0.f, 0.f, 0.f, 0.f};
            if (d < bp.N) {
                f2v = gather_warp(bp, d, lane, bp.gb2);
                f1v = ld4(bp.f1 + d * D + lane * 4);
            }
            *(float4*)(sA + r * 256 + lane * 4) = f1v;
            *(float4*)(sA + r * 256 + 128 + lane * 4) = f2v;
        }
        __syncthreads();
        int col = tid & 127;
        int r0 = (tid >> 7) << 3;
        #pragma unroll
        for (int cb = 0; cb < 2; cb++) {
            int o = cb * 128 + col;
            float bo = bp.cb[o];
            float acc[8];
            #pragma unroll
            for (int r = 0; r < 8; r++) acc[r] = bo;
            const float* w = bp.cw + o * 256;
            #pragma unroll 4
            for (int k = 0; k < 256; k++) {
                float wv = w[k];
                #pragma unroll
                for (int r = 0; r < 8; r++) acc[r] = fmaf(sA[(r0 + r) * 256 + k], wv, acc[r]);
            }
            #pragma unroll
            for (int r = 0; r < 8; r++)
                if (rb + r0 + r < bp.N) bp.fea[(rb + r0 + r) * 256 + o] = acc[r];
        }
        __syncthreads();
    }
}

// ---------------- final matmul (split-K) ----------------
__device__ void final_phase(const float* cir, const float* dis, float* out,
                            float* sA, int tid) {
    for (int t = blockIdx.x; t < (NCIR + 15) / 16; t += NB) {
        int ib = t * 16;
        #pragma unroll
        for (int q = 0; q < 16; q++) {
            int idx = q * 256 + tid;
            int i = ib + (idx >> 8);
            sA[idx] = (i < NCIR) ? cir[i * 256 + (idx & 255)] : 0.f;
        }
        __syncthreads();
        int j = tid & 127;
        int half = tid >> 7;
        float acc[16];
        #pragma unroll
        for (int r = 0; r < 16; r++) acc[r] = 0.f;
        if (j < NDIS) {
            const float* dr = dis + j * 256 + half * 128;
            #pragma unroll 4
            for (int k = 0; k < 128; k++) {
                float dv = dr[k];
                #pragma unroll
                for (int r = 0; r < 16; r++)
                    acc[r] = fmaf(sA[r * 256 + half * 128 + k], dv, acc[r]);
            }
        }
        __syncthreads();
        if (half == 1 && j < NDIS) {
            #pragma unroll
            for (int r = 0; r < 16; r++) sA[j * 16 + r] = acc[r];
        }
        __syncthreads();
        if (half == 0 && j < NDIS) {
            #pragma unroll
            for (int r = 0; r < 16; r++)
                if (ib + r < NCIR) out[(ib + r) * NDIS + j] = acc[r] + sA[j * 16 + r];
        }
        __syncthreads();
    }
}

// ---------------- mega kernel ----------------
__global__ __launch_bounds__(256, 2) void k_mega(Pair P, float* out) {
    __shared__ float sbuf[4160];
    __shared__ unsigned s_sense;
    const int tid = threadIdx.x;
    const int lane = tid & 31;
    const int gid = blockIdx.x * 256 + tid;
    const int wgid = blockIdx.x * 8 + (tid >> 5);
    if (tid == 0) s_sense = g_sense;
    __syncthreads();

    const BP& b0 = P.b[0];
    const BP& b1 = P.b[1];
    const int NT = b0.N + b1.N;

    // A: init + va/cvec precompute + GEMM1 (h = x @ W1)
    for (int i = gid; i < 1024; i += NB * 256) {
        if (i < b0.N) { b0.deg[i] = 1.f; b0.cnt[i] = 0; }
        if (i < b1.N) { b1.deg[i] = 1.f; b1.cnt[i] = 0; }
        if (i == 0) { b0.ewsum[0] = 0.f; b1.ewsum[0] = 0.f; }
    }
    for (int tt = wgid; tt < 4112; tt += NWARP) prep_warp(P, tt, lane);
    gemm_phase(sbuf, tid, b0.x, b0.gw1, b0.h, b0.N, b1.x, b1.gw1, b1.h, b1.N, 128);
    gsync(&s_sense);

    // B: edge gather + degree + histogram
    edge1_branch(b0, gid);
    edge1_branch(b1, gid);
    gsync(&s_sense);

    // C: scan
    if (blockIdx.x < 2) scan_branch(P.b[blockIdx.x], sbuf, tid);
    gsync(&s_sense);

    // D: CSR placement
    for (int e = gid; e < b0.E; e += NB * 256) {
        int d = b0.edges[b0.E + e];
        b0.eid[atomicAdd(b0.cursor + d, 1)] = e;
    }
    for (int e = gid; e < b1.E; e += NB * 256) {
        int d = b1.edges[b1.E + e];
        b1.eid[atomicAdd(b1.cursor + d, 1)] = e;
    }
    gsync(&s_sense);

    // E: GCN1 gather -> f1 (warp per node)
    for (int task = wgid; task < NT; task += NWARP) {
        int br = task >= b0.N;
        const BP& bp = P.b[br];
        int d = br ? task - b0.N : task;
        float4 r = gather_warp(bp, d, lane, bp.gb1);
        *(float4*)(bp.f1 + d * D + lane * 4) = r;
    }
    gsync(&s_sense);

    // F: GEMM2 (h2 = f1 @ aw) + attention dots (an = f1 . va)
    gemm_phase(sbuf, tid, b0.f1, b0.aw, b0.h2, b0.N, b1.f1, b1.aw, b1.h2, b1.N, HD);
    for (int task = wgid; task < NT; task += NWARP) {
        int br = task >= b0.N;
        an_warp(P.b[br], br ? task - b0.N : task, lane);
    }
    gsync(&s_sense);

    // G: fused GAT -> att (warp per node)
    for (int task = wgid; task < NT; task += NWARP) {
        int br = task >= b0.N;
        gat_warp(P.b[br], br ? task - b0.N : task, lane);
    }
    gsync(&s_sense);

    // H: GEMM3 (h = att @ W2)
    gemm_phase(sbuf, tid, b0.att, b0.gw2, b0.h, b0.N, b1.att, b1.gw2, b1.h, b1.N, 128);
    gsync(&s_sense);

    // I: GCN2 gather + CNN head (merged, f2 stays in smem)
    gather2_cnn_phase(P, sbuf, tid);
    gsync(&s_sense);

    // J: final matmul
    final_phase(b0.fea, b1.fea, out, sbuf, tid);
}

// -------------------- host --------------------
static void fill_bp(BP& bp, const float* x, const float* mat, const int* edges,
                    const float* gw1, const float* gb1,
                    const float* aw, const float* asrc, const float* adst,
                    const float* aedge, const float* awe, const float* ab,
                    const float* gw2, const float* gb2,
                    const float* cw, const float* cb,
                    float* fea, int N, int E, float*& S) {
    bp.x = x; bp.mat = mat; bp.edges = edges;
    bp.gw1 = gw1; bp.gb1 = gb1; bp.aw = aw;
    bp.asrc = asrc; bp.adst = adst; bp.aedge = aedge;
    bp.awe = awe; bp.ab = ab; bp.gw2 = gw2; bp.gb2 = gb2;
    bp.cw = cw; bp.cb = cb;
    bp.fea = fea; bp.N = N; bp.E = E;
    bp.ew = S;        S += pad4(E);
    bp.deg = S;       S += pad4(N);
    bp.h = S;         S += pad4(N * D);
    bp.f1 = S;        S += pad4(N * D);
    bp.h2 = S;        S += pad4(N * HD);
    bp.an_src = S;    S += pad4(N * H);
    bp.an_dst = S;    S += pad4(N * H);
    bp.att = S;       S += pad4(N * D);
    bp.vsrc = S;      S += HD;
    bp.vdst = S;      S += HD;
    bp.cvec = S;      S += 8;
    bp.ewsum = S;     S += 8;
    bp.cnt = (int*)S;    S += pad4(N);
    bp.rowptr = (int*)S; S += pad4(N + 1);
    bp.cursor = (int*)S; S += pad4(N);
    bp.eid = (int*)S;    S += pad4(E);
}

extern "C" void kernel_launch(void* const* d_in, const int* in_sizes, int n_in,
                              void* d_out, int out_size) {
    float* S = nullptr;
    cudaGetSymbolAddress((void**)&S, g_scratch);

    const float* in_f[28];
    for (int i = 0; i < 28; i++) in_f[i] = (const float*)d_in[i];
    const int* cc_edges = (const int*)d_in[28];
    const int* dd_edges = (const int*)d_in[29];

    float* out = (float*)d_out;
    float* cirfea = out + NCIR * NDIS;
    float* disfea = cirfea + NCIR * 256;

    Pair P;
    float* cur = S;
    fill_bp(P.b[0], in_f[0], in_f[2], cc_edges,
            in_f[4], in_f[5], in_f[6], in_f[7], in_f[8], in_f[9], in_f[10], in_f[11],
            in_f[12], in_f[13], in_f[24], in_f[25], cirfea, NCIR, ECC, cur);
    fill_bp(P.b[1], in_f[1], in_f[3], dd_edges,
            in_f[14], in_f[15], in_f[16], in_f[17], in_f[18], in_f[19], in_f[20], in_f[21],
            in_f[22], in_f[23], in_f[26], in_f[27], disfea, NDIS, EDD, cur);

    k_mega<<<NB, 256>>>(P, out);
}

// round 6
// speedup vs baseline: 1.0310x; 1.0310x over previous
#include <cuda_runtime.h>
#include <math.h>

#define D 128
#define HD 1024
#define H 8
#define NCIR 585
#define NDIS 88
#define ECC 20000
#define EDD 3000
#define GE0 79        // cdiv(ECC,256)
#define GE1 12        // cdiv(EDD,256)
#define GEDGE (GE0 + GE1)          // 91
#define GT0 37        // cdiv(NCIR,16)
#define GT1 6         // cdiv(NDIS,16)
#define GTILE (GT0 + GT1)          // 43
#define NT (NCIR + NDIS)           // 673
#define FULL 0xffffffffu

__device__ __align__(16) float g_scratch[1720000];

struct BP {
    const float *x, *mat;
    const int *edges;
    const float *gb1, *ab, *gb2, *cw, *cb;
    const float *asrc, *adst, *aedge, *awe;
    const float *gw1, *aw, *gw2;
    float *fea;
    int N, E;
    float *ew, *deg, *h, *f1, *h2, *an_src, *an_dst, *att, *cvec, *ewsum;
    float *vsrc, *vdst;
    int *cnt, *rowptr, *cursor, *eid;
};
struct Pair { BP b[2]; };

static inline int pad4(int n) { return (n + 3) & ~3; }

// ---------------- helpers ----------------
__device__ __forceinline__ float4 ld4(const float* p) { return *(const float4*)p; }
__device__ __forceinline__ float wsum(float v) {
    #pragma unroll
    for (int o = 16; o; o >>= 1) v += __shfl_xor_sync(FULL, v, o);
    return v;
}
__device__ __forceinline__ float wmax(float v) {
    #pragma unroll
    for (int o = 16; o; o >>= 1) v = fmaxf(v, __shfl_xor_sync(FULL, v, o));
    return v;
}

// ---------------- GEMM tile: C[rb:rb+16, cb:cb+128] = A[*,128] @ W[128,ncols] ----------------
__device__ void gemm_tile(float* sA, int tid, const float* __restrict__ A,
                          const float* __restrict__ W, float* __restrict__ C,
                          int M, int ncols, int rb, int cb) {
    #pragma unroll
    for (int q = 0; q < 8; q++) {
        int idx = q * 256 + tid;
        int r = idx >> 7, k = idx & 127;
        sA[idx] = (rb + r < M) ? A[(rb + r) * 128 + k] : 0.f;
    }
    __syncthreads();
    int col = cb + (tid & 127);
    int r0 = (tid >> 7) << 3;
    float acc[8] = {0.f, 0.f, 0.f, 0.f, 0.f, 0.f, 0.f, 0.f};
    #pragma unroll 8
    for (int k = 0; k < 128; k++) {
        float w = W[k * ncols + col];
        #pragma unroll
        for (int r = 0; r < 8; r++) acc[r] = fmaf(sA[(r0 + r) * 128 + k], w, acc[r]);
    }
    #pragma unroll
    for (int r = 0; r < 8; r++)
        if (rb + r0 + r < M) C[(rb + r0 + r) * ncols + col] = acc[r];
}

// ---------------- va vectors + cvec precompute (warp task) ----------------
__device__ void prep_warp(const Pair& P, int tt, int lane) {
    if (tt < 4096) {
        int br = tt >> 11; int r = tt & 2047;
        int type = r >> 10; r &= 1023;
        int hh = r >> 7; int k = r & 127;
        const BP& bp = P.b[br];
        const float* avec = type ? bp.adst : bp.asrc;
        float* vout = type ? bp.vdst : bp.vsrc;
        float4 w4 = ld4(bp.aw + k * HD + hh * D + lane * 4);
        float4 a4 = ld4(avec + hh * D + lane * 4);
        float s = w4.x * a4.x + w4.y * a4.y + w4.z * a4.z + w4.w * a4.w;
        s = wsum(s);
        if (lane == 0) vout[hh * D + k] = s;
    } else {
        int r = tt - 4096;
        if (r >= 16) return;
        int br = r >> 3; int hh = r & 7;
        const BP& bp = P.b[br];
        float4 a = ld4(bp.awe + hh * D + lane * 4);
        float4 e = ld4(bp.aedge + hh * D + lane * 4);
        float s = a.x * e.x + a.y * e.y + a.z * e.z + a.w * e.w;
        s = wsum(s);
        if (lane == 0) bp.cvec[hh] = s;
    }
}

// ---------------- warp-per-node GCN gather ----------------
__device__ float4 gather_warp(const BP& bp, int d, int lane, const float* bias) {
    float dd = bp.deg[d];
    float4 hv = ld4(bp.h + d * D + lane * 4);
    float4 b4 = ld4(bias + lane * 4);
    float sl = dd * dd;
    float4 acc;
    acc.x = fmaf(hv.x, sl, b4.x); acc.y = fmaf(hv.y, sl, b4.y);
    acc.z = fmaf(hv.z, sl, b4.z); acc.w = fmaf(hv.w, sl, b4.w);
    int rp = bp.rowptr[d], re = bp.rowptr[d + 1];
    for (int base = rp; base < re; base += 32) {
        int c = base + lane;
        int s = d; float nrm = 0.f;
        if (c < re) {
            int e = bp.eid[c];
            s = bp.edges[e];
            nrm = bp.deg[s] * bp.ew[e] * dd;
        }
        int cnt = min(32, re - base);
        for (int t = 0; t < cnt; t++) {
            int ss = __shfl_sync(FULL, s, t);
            float nn = __shfl_sync(FULL, nrm, t);
            float4 v = ld4(bp.h + ss * D + lane * 4);
            acc.x = fmaf(v.x, nn, acc.x); acc.y = fmaf(v.y, nn, acc.y);
            acc.z = fmaf(v.z, nn, acc.z); acc.w = fmaf(v.w, nn, acc.w);
        }
    }
    acc.x = fmaxf(acc.x, 0.f); acc.y = fmaxf(acc.y, 0.f);
    acc.z = fmaxf(acc.z, 0.f); acc.w = fmaxf(acc.w, 0.f);
    return acc;
}

// ---------------- warp-per-node attention dots (an = f1 . va) ----------------
__device__ void an_warp(const BP& bp, int n, int lane) {
    float4 f = ld4(bp.f1 + n * D + lane * 4);
    #pragma unroll
    for (int hh = 0; hh < H; hh++) {
        float4 a = ld4(bp.vsrc + hh * D + lane * 4);
        float4 b = ld4(bp.vdst + hh * D + lane * 4);
        float s1 = f.x * a.x + f.y * a.y + f.z * a.z + f.w * a.w;
        float s2 = f.x * b.x + f.y * b.y + f.z * b.z + f.w * b.w;
        s1 = wsum(s1); s2 = wsum(s2);
        if (lane == 0) { bp.an_src[n * H + hh] = s1; bp.an_dst[n * H + hh] = s2; }
    }
}

// ---------------- warp-per-node fused GAT ----------------
__device__ void gat_warp(const BP& bp, int d, int lane) {
    int rp = bp.rowptr[d];
    int deg = bp.rowptr[d + 1] - rp;
    int total = deg + 1;
    float meanw = bp.ewsum[0] / (float)bp.E;
    float ad[H], ch[H], m[H], den[H];
    #pragma unroll
    for (int hh = 0; hh < H; hh++) {
        ad[hh] = bp.an_dst[d * H + hh];
        ch[hh] = bp.cvec[hh];
        m[hh] = -INFINITY; den[hh] = 0.f;
    }
    for (int base = 0; base < total; base += 32) {
        int c = base + lane;
        bool valid = c < total;
        int s = d; float w = meanw;
        if (c < deg) { int e = bp.eid[rp + c]; s = bp.edges[e]; w = bp.ew[e]; }
        #pragma unroll
        for (int hh = 0; hh < H; hh++) {
            float l = bp.an_src[s * H + hh] + ad[hh] + w * ch[hh];
            l = (l >= 0.f) ? l : 0.2f * l;
            if (!valid) l = -INFINITY;
            float cm = wmax(l);
            float nm = fmaxf(m[hh], cm);
            float ex = valid ? __expf(l - nm) : 0.f;
            float ls = wsum(ex);
            den[hh] = den[hh] * __expf(m[hh] - nm) + ls;
            m[hh] = nm;
        }
    }
    float inv[H];
    #pragma unroll
    for (int hh = 0; hh < H; hh++) inv[hh] = 1.f / (den[hh] + 1e-16f);
    float4 acc = {0.f, 0.f, 0.f, 0.f};
    for (int base = 0; base < total; base += 32) {
        int c = base + lane;
        bool valid = c < total;
        int s = d; float w = meanw;
        if (c < deg) { int e = bp.eid[rp + c]; s = bp.edges[e]; w = bp.ew[e]; }
        float cf[H];
        #pragma unroll
        for (int hh = 0; hh < H; hh++) {
            float l = bp.an_src[s * H + hh] + ad[hh] + w * ch[hh];
            l = (l >= 0.f) ? l : 0.2f * l;
            cf[hh] = valid ? __expf(l - m[hh]) * inv[hh] : 0.f;
        }
        int cnt = min(32, total - base);
        for (int t = 0; t < cnt; t++) {
            int ss = __shfl_sync(FULL, s, t);
            const float4* hrow = (const float4*)(bp.h2 + ss * HD) + lane;
            #pragma unroll
            for (int hh = 0; hh < H; hh++) {
                float c_h = __shfl_sync(FULL, cf[hh], t);
                float4 v = hrow[hh * 32];
                acc.x = fmaf(v.x, c_h, acc.x); acc.y = fmaf(v.y, c_h, acc.y);
                acc.z = fmaf(v.z, c_h, acc.z); acc.w = fmaf(v.w, c_h, acc.w);
            }
        }
    }
    float4 b4 = ld4(bp.ab + lane * 4);
    float4 o;
    o.x = fmaxf(fmaf(acc.x, 0.125f, b4.x), 0.f);
    o.y = fmaxf(fmaf(acc.y, 0.125f, b4.y), 0.f);
    o.z = fmaxf(fmaf(acc.z, 0.125f, b4.z), 0.f);
    o.w = fmaxf(fmaf(acc.w, 0.125f, b4.w), 0.f);
    *(float4*)(bp.att + d * D + lane * 4) = o;
}

// ============ K1: edge gather+deg+hist || GEMM1 || va/cvec prep ============
__global__ void k_phase1(Pair P) {
    __shared__ float sA[2048];
    int tid = threadIdx.x, lane = tid & 31, wid = tid >> 5;
    int b = blockIdx.x;
    if (b < GEDGE) {
        int br = b >= GE0;
        const BP& bp = P.b[br];
        int e = (br ? b - GE0 : b) * 256 + tid;
        float w = 0.f;
        if (e < bp.E) {
            int s = bp.edges[e], d = bp.edges[bp.E + e];
            w = bp.mat[s * bp.N + d];
            bp.ew[e] = w;
            atomicAdd(bp.deg + d, w);
            atomicAdd(bp.cnt + d, 1);
        }
        float ws = w;
        #pragma unroll
        for (int o = 16; o; o >>= 1) ws += __shfl_down_sync(FULL, ws, o);
        if (lane == 0 && ws != 0.f) atomicAdd(bp.ewsum, ws);
    } else if (b < GEDGE + GTILE) {
        int t = b - GEDGE;
        int br = t >= GT0;
        const BP& bp = P.b[br];
        gemm_tile(sA, tid, bp.x, bp.gw1, bp.h, bp.N, 128, (br ? t - GT0 : t) << 4, 0);
    } else {
        int wt = (b - GEDGE - GTILE) * 8 + wid;
        if (wt < 4112) prep_warp(P, wt, lane);
    }
}

// ============ K2: scan -> rowptr/cursor, deg -> rsqrt(deg + self-loop) ============
__global__ void k_scan(Pair P) {
    __shared__ int sc[256];
    const BP& bp = P.b[blockIdx.x];
    int tid = threadIdx.x;
    int base = tid * 4;
    int v[4]; int s = 0;
    #pragma unroll
    for (int q = 0; q < 4; q++) {
        v[q] = (base + q < bp.N) ? bp.cnt[base + q] : 0;
        s += v[q];
    }
    sc[tid] = s; __syncthreads();
    #pragma unroll
    for (int off = 1; off < 256; off <<= 1) {
        int t2 = (tid >= off) ? sc[tid - off] : 0;
        __syncthreads();
        sc[tid] += t2;
        __syncthreads();
    }
    int run = sc[tid] - s;
    #pragma unroll
    for (int q = 0; q < 4; q++) {
        run += v[q];
        if (base + q < bp.N) {
            bp.rowptr[base + q + 1] = run;
            bp.cursor[base + q] = run - v[q];
            bp.deg[base + q] = rsqrtf(bp.deg[base + q] + 1.0f);  // +1 self-loop
        }
    }
    if (tid == 0) bp.rowptr[0] = 0;
}

// ============ K3: CSR placement + reset cnt for next call ============
__global__ void k_edge2(Pair P) {
    int tid = threadIdx.x;
    int b = blockIdx.x;
    int gid = b * 256 + tid;
    if (gid < P.b[0].N) P.b[0].cnt[gid] = 0;
    if (gid < P.b[1].N) P.b[1].cnt[gid] = 0;
    int br = b >= GE0;
    const BP& bp = P.b[br];
    int e = (br ? b - GE0 : b) * 256 + tid;
    if (e < bp.E) {
        int d = bp.edges[bp.E + e];
        bp.eid[atomicAdd(bp.cursor + d, 1)] = e;
    }
}

// ============ K4: GCN1 gather -> f1 ============
__global__ void k_gather1(Pair P) {
    int lane = threadIdx.x & 31;
    int task = blockIdx.x * 8 + (threadIdx.x >> 5);
    if (task >= NT) return;
    int br = task >= P.b[0].N;
    const BP& bp = P.b[br];
    int d = br ? task - P.b[0].N : task;
    float4 r = gather_warp(bp, d, lane, bp.gb1);
    *(float4*)(bp.f1 + d * D + lane * 4) = r;
}

// ============ K5: GEMM2 (h2 = f1@aw) || attention dots ============
#define G2 (GT0 * 8 + GT1 * 8)    // 344
__global__ void k_gemm2attn(Pair P) {
    __shared__ float sA[2048];
    int tid = threadIdx.x;
    int b = blockIdx.x;
    if (b < G2) {
        int br = b >= GT0 * 8;
        int t = br ? b - GT0 * 8 : b;
        const BP& bp = P.b[br];
        gemm_tile(sA, tid, bp.f1, bp.aw, bp.h2, bp.N, HD, (t >> 3) << 4, (t & 7) << 7);
    } else {
        int task = (b - G2) * 8 + (tid >> 5);
        if (task < NT) {
            int br = task >= P.b[0].N;
            an_warp(P.b[br], br ? task - P.b[0].N : task, tid & 31);
        }
    }
}

// ============ K6: fused GAT -> att ============
__global__ void k_gat(Pair P) {
    int task = blockIdx.x * 4 + (threadIdx.x >> 5);
    if (task >= NT) return;
    int br = task >= P.b[0].N;
    gat_warp(P.b[br], br ? task - P.b[0].N : task, threadIdx.x & 31);
}

// ============ K7: GEMM3 (h = att@gw2) ============
__global__ void k_gemm3(Pair P) {
    __shared__ float sA[2048];
    int tid = threadIdx.x;
    int t = blockIdx.x;
    int br = t >= GT0;
    const BP& bp = P.b[br];
    gemm_tile(sA, tid, bp.att, bp.gw2, bp.h, bp.N, 128, (br ? t - GT0 : t) << 4, 0);
}

// ============ K8: GCN2 gather + CNN head (f2 stays in smem) ============
__global__ void k_g2cnn(Pair P) {
    __shared__ float sA[4096];
    int tid = threadIdx.x, wid = tid >> 5, lane = tid & 31;
    int t = blockIdx.x;
    int br = t >= GT0;
    const BP& bp = P.b[br];
    int rb = (br ? t - GT0 : t) << 4;
    #pragma unroll
    for (int q = 0; q < 2; q++) {
        int r = 2 * wid + q;
        int d = rb + r;
        float4 f2v = {0.f, 0.f, 0.f, 0.f};
        float4 f1v = {0.f, 0.f, 0.f, 0.f};
        if (d < bp.N) {
            f2v = gather_warp(bp, d, lane, bp.gb2);
            f1v = ld4(bp.f1 + d * D + lane * 4);
        }
        *(float4*)(sA + r * 256 + lane * 4) = f1v;
        *(float4*)(sA + r * 256 + 128 + lane * 4) = f2v;
    }
    __syncthreads();
    int col = tid & 127;
    int r0 = (tid >> 7) << 3;
    #pragma unroll
    for (int cb = 0; cb < 2; cb++) {
        int o = cb * 128 + col;
        float bo = bp.cb[o];
        float acc[8];
        #pragma unroll
        for (int r = 0; r < 8; r++) acc[r] = bo;
        const float* w = bp.cw + o * 256;
        #pragma unroll 8
        for (int k = 0; k < 256; k++) {
            float wv = w[k];
            #pragma unroll
            for (int r = 0; r < 8; r++) acc[r] = fmaf(sA[(r0 + r) * 256 + k], wv, acc[r]);
        }
        #pragma unroll
        for (int r = 0; r < 8; r++)
            if (rb + r0 + r < bp.N) bp.fea[(rb + r0 + r) * 256 + o] = acc[r];
    }
}

// ============ K9: final matmul + state resets for next call ============
__global__ void k_final(Pair P, float* __restrict__ out) {
    __shared__ float sA[4096];
    int tid = threadIdx.x;
    int t = blockIdx.x;
    if (t >= GT0) {
        int idx = (t - GT0) * 256 + tid;
        if (idx < P.b[0].N) P.b[0].deg[idx] = 0.f;
        if (idx < P.b[1].N) P.b[1].deg[idx] = 0.f;
        if (idx == 0) { P.b[0].ewsum[0] = 0.f; P.b[1].ewsum[0] = 0.f; }
        return;
    }
    const float* cir = P.b[0].fea;
    const float* dis = P.b[1].fea;
    int ib = t * 16;
    #pragma unroll
    for (int q = 0; q < 16; q++) {
        int idx = q * 256 + tid;
        int i = ib + (idx >> 8);
        sA[idx] = (i < NCIR) ? cir[i * 256 + (idx & 255)] : 0.f;
    }
    __syncthreads();
    int j = tid & 127;
    int half = tid >> 7;
    float acc[16];
    #pragma unroll
    for (int r = 0; r < 16; r++) acc[r] = 0.f;
    if (j < NDIS) {
        const float* dr = dis + j * 256 + half * 128;
        #pragma unroll 8
        for (int k = 0; k < 128; k++) {
            float dv = dr[k];
            #pragma unroll
            for (int r = 0; r < 16; r++)
                acc[r] = fmaf(sA[r * 256 + half * 128 + k], dv, acc[r]);
        }
    }
    __syncthreads();
    if (half == 1 && j < NDIS) {
        #pragma unroll
        for (int r = 0; r < 16; r++) sA[j * 16 + r] = acc[r];
    }
    __syncthreads();
    if (half == 0 && j < NDIS) {
        #pragma unroll
        for (int r = 0; r < 16; r++)
            if (ib + r < NCIR) out[(ib + r) * NDIS + j] = acc[r] + sA[j * 16 + r];
    }
}

// -------------------- host --------------------
static void fill_bp(BP& bp, const float* x, const float* mat, const int* edges,
                    const float* gw1, const float* gb1,
                    const float* aw, const float* asrc, const float* adst,
                    const float* aedge, const float* awe, const float* ab,
                    const float* gw2, const float* gb2,
                    const float* cw, const float* cb,
                    float* fea, int N, int E, float*& S) {
    bp.x = x; bp.mat = mat; bp.edges = edges;
    bp.gw1 = gw1; bp.gb1 = gb1; bp.aw = aw;
    bp.asrc = asrc; bp.adst = adst; bp.aedge = aedge;
    bp.awe = awe; bp.ab = ab; bp.gw2 = gw2; bp.gb2 = gb2;
    bp.cw = cw; bp.cb = cb;
    bp.fea = fea; bp.N = N; bp.E = E;
    bp.ew = S;        S += pad4(E);
    bp.deg = S;       S += pad4(N);
    bp.h = S;         S += pad4(N * D);
    bp.f1 = S;        S += pad4(N * D);
    bp.h2 = S;        S += pad4(N * HD);
    bp.an_src = S;    S += pad4(N * H);
    bp.an_dst = S;    S += pad4(N * H);
    bp.att = S;       S += pad4(N * D);
    bp.vsrc = S;      S += HD;
    bp.vdst = S;      S += HD;
    bp.cvec = S;      S += 8;
    bp.ewsum = S;     S += 8;
    bp.cnt = (int*)S;    S += pad4(N);
    bp.rowptr = (int*)S; S += pad4(N + 1);
    bp.cursor = (int*)S; S += pad4(N);
    bp.eid = (int*)S;    S += pad4(E);
}

extern "C" void kernel_launch(void* const* d_in, const int* in_sizes, int n_in,
                              void* d_out, int out_size) {
    float* S = nullptr;
    cudaGetSymbolAddress((void**)&S, g_scratch);

    const float* in_f[28];
    for (int i = 0; i < 28; i++) in_f[i] = (const float*)d_in[i];
    const int* cc_edges = (const int*)d_in[28];
    const int* dd_edges = (const int*)d_in[29];

    float* out = (float*)d_out;
    float* cirfea = out + NCIR * NDIS;
    float* disfea = cirfea + NCIR * 256;

    Pair P;
    float* cur = S;
    fill_bp(P.b[0], in_f[0], in_f[2], cc_edges,
            in_f[4], in_f[5], in_f[6], in_f[7], in_f[8], in_f[9], in_f[10], in_f[11],
            in_f[12], in_f[13], in_f[24], in_f[25], cirfea, NCIR, ECC, cur);
    fill_bp(P.b[1], in_f[1], in_f[3], dd_edges,
            in_f[14], in_f[15], in_f[16], in_f[17], in_f[18], in_f[19], in_f[20], in_f[21],
            in_f[22], in_f[23], in_f[26], in_f[27], disfea, NDIS, EDD, cur);

    int prep_blocks = (4112 + 7) / 8;                 // 514
    k_phase1<<<GEDGE + GTILE + prep_blocks, 256>>>(P);
    k_scan<<<2, 256>>>(P);
    k_edge2<<<GEDGE, 256>>>(P);
    k_gather1<<<(NT + 7) / 8, 256>>>(P);
    k_gemm2attn<<<G2 + (NT + 7) / 8, 256>>>(P);
    k_gat<<<(NT + 3) / 4, 128>>>(P);
    k_gemm3<<<GTILE, 256>>>(P);
    k_g2cnn<<<GTILE, 256>>>(P);
    k_final<<<GT0 + 3, 256>>>(P, out);
}

// round 7
// speedup vs baseline: 1.6797x; 1.6292x over previous
#include <cuda_runtime.h>
#include <math.h>

#define D 128
#define HD 1024
#define H 8
#define NCIR 585
#define NDIS 88
#define ECC 20000
#define EDD 3000
#define GE0 79
#define GE1 12
#define GEDGE (GE0 + GE1)   // 91
#define GT0 37
#define GT1 6
#define GTILE (GT0 + GT1)   // 43
#define GPREP 86
#define NT (NCIR + NDIS)    // 673
#define G2 (GT0 * 8 + GT1 * 8)  // 344
#define FULL 0xffffffffu

__device__ __align__(16) float g_scratch[1720000];

struct BP {
    const float *x, *mat;
    const int *edges;
    const float *gb1, *ab, *gb2, *cw, *cb;
    const float *asrc, *adst, *aedge, *awe;
    const float *gw1, *aw, *gw2;
    float *fea;
    int N, E;
    float *ew, *deg, *h, *f1, *h2, *an_src, *an_dst, *att, *f2, *cvec, *ewsum;
    float *vsrc, *vdst;
    int *cnt, *rowptr, *cursor, *eid;
};
struct Pair { BP b[2]; };

static inline int pad4(int n) { return (n + 3) & ~3; }

__device__ __forceinline__ float4 ld4(const float* p) { return *(const float4*)p; }
__device__ __forceinline__ float wsum(float v) {
    #pragma unroll
    for (int o = 16; o; o >>= 1) v += __shfl_xor_sync(FULL, v, o);
    return v;
}

// ---- GEMM tile: C[rb:rb+16, cb:cb+128] = A[*,128] @ W[128,ncols], 256 thr ----
__device__ void gemm_tile(float* sA, int tid, const float* __restrict__ A,
                          const float* __restrict__ W, float* __restrict__ C,
                          int M, int ncols, int rb, int cb) {
    #pragma unroll
    for (int q = 0; q < 8; q++) {
        int idx = q * 256 + tid;
        int r = idx >> 7, k = idx & 127;
        sA[idx] = (rb + r < M) ? A[(rb + r) * 128 + k] : 0.f;
    }
    __syncthreads();
    int col = cb + (tid & 127);
    int r0 = (tid >> 7) << 3;
    float acc[8] = {0.f, 0.f, 0.f, 0.f, 0.f, 0.f, 0.f, 0.f};
    #pragma unroll 8
    for (int k = 0; k < 128; k++) {
        float w = W[k * ncols + col];
        #pragma unroll
        for (int r = 0; r < 8; r++) acc[r] = fmaf(sA[(r0 + r) * 128 + k], w, acc[r]);
    }
    #pragma unroll
    for (int r = 0; r < 8; r++)
        if (rb + r0 + r < M) C[(rb + r0 + r) * ncols + col] = acc[r];
}

// ---- va/cvec precompute (warp task) ----
__device__ void prep_warp(const Pair& P, int tt, int lane) {
    if (tt < 4096) {
        int br = tt >> 11; int r = tt & 2047;
        int type = r >> 10; r &= 1023;
        int hh = r >> 7; int k = r & 127;
        const BP& bp = P.b[br];
        const float* avec = type ? bp.adst : bp.asrc;
        float* vout = type ? bp.vdst : bp.vsrc;
        float4 w4 = ld4(bp.aw + k * HD + hh * D + lane * 4);
        float4 a4 = ld4(avec + hh * D + lane * 4);
        float s = wsum(w4.x * a4.x + w4.y * a4.y + w4.z * a4.z + w4.w * a4.w);
        if (lane == 0) vout[hh * D + k] = s;
    } else {
        int r = tt - 4096;
        if (r >= 16) return;
        int br = r >> 3; int hh = r & 7;
        const BP& bp = P.b[br];
        float4 a = ld4(bp.awe + hh * D + lane * 4);
        float4 e = ld4(bp.aedge + hh * D + lane * 4);
        float s = wsum(a.x * e.x + a.y * e.y + a.z * e.z + a.w * e.w);
        if (lane == 0) bp.cvec[hh] = s;
    }
}

// ---- attention node dots: an = f1 . va (warp task) ----
__device__ void an_warp(const BP& bp, int n, int lane) {
    float4 f = ld4(bp.f1 + n * D + lane * 4);
    #pragma unroll
    for (int hh = 0; hh < H; hh++) {
        float4 a = ld4(bp.vsrc + hh * D + lane * 4);
        float4 b = ld4(bp.vdst + hh * D + lane * 4);
        float s1 = wsum(f.x * a.x + f.y * a.y + f.z * a.z + f.w * a.w);
        float s2 = wsum(f.x * b.x + f.y * b.y + f.z * b.z + f.w * b.w);
        if (lane == 0) { bp.an_src[n * H + hh] = s1; bp.an_dst[n * H + hh] = s2; }
    }
}

// ============ K1: edge gather/deg/hist || GEMM1 || prep ============
__global__ void k_phase1(Pair P) {
    __shared__ float sA[2048];
    int tid = threadIdx.x, lane = tid & 31, wid = tid >> 5;
    int b = blockIdx.x;
    if (b < GEDGE) {
        int br = b >= GE0;
        const BP& bp = P.b[br];
        int e = (br ? b - GE0 : b) * 256 + tid;
        float w = 0.f;
        if (e < bp.E) {
            int s = bp.edges[e], d = bp.edges[bp.E + e];
            w = bp.mat[s * bp.N + d];
            bp.ew[e] = w;
            atomicAdd(bp.deg + d, w);
            atomicAdd(bp.cnt + d, 1);
        }
        float ws = w;
        #pragma unroll
        for (int o = 16; o; o >>= 1) ws += __shfl_down_sync(FULL, ws, o);
        if (lane == 0 && ws != 0.f) atomicAdd(bp.ewsum, ws);
    } else if (b < GEDGE + GTILE) {
        int t = b - GEDGE;
        int br = t >= GT0;
        const BP& bp = P.b[br];
        gemm_tile(sA, tid, bp.x, bp.gw1, bp.h, bp.N, 128, (br ? t - GT0 : t) << 4, 0);
    } else {
        int gw = (b - GEDGE - GTILE) * 8 + wid;
        for (int tt = gw; tt < 4112; tt += GPREP * 8) prep_warp(P, tt, lane);
    }
}

// ============ K2: scan -> rowptr/cursor, deg -> rsqrt(deg+1) ============
__global__ void k_scan(Pair P) {
    __shared__ int sc[256];
    const BP& bp = P.b[blockIdx.x];
    int tid = threadIdx.x;
    int base = tid * 4;
    int v[4]; int s = 0;
    #pragma unroll
    for (int q = 0; q < 4; q++) {
        v[q] = (base + q < bp.N) ? bp.cnt[base + q] : 0;
        s += v[q];
    }
    sc[tid] = s; __syncthreads();
    #pragma unroll
    for (int off = 1; off < 256; off <<= 1) {
        int t2 = (tid >= off) ? sc[tid - off] : 0;
        __syncthreads();
        sc[tid] += t2;
        __syncthreads();
    }
    int run = sc[tid] - s;
    #pragma unroll
    for (int q = 0; q < 4; q++) {
        run += v[q];
        if (base + q < bp.N) {
            bp.rowptr[base + q + 1] = run;
            bp.cursor[base + q] = run - v[q];
            bp.deg[base + q] = rsqrtf(bp.deg[base + q] + 1.0f);
        }
    }
    if (tid == 0) bp.rowptr[0] = 0;
}

// ============ K3: CSR placement + cnt reset ============
__global__ void k_edge2(Pair P) {
    int tid = threadIdx.x;
    int b = blockIdx.x;
    int gid = b * 256 + tid;
    if (gid < P.b[0].N) P.b[0].cnt[gid] = 0;
    if (gid < P.b[1].N) P.b[1].cnt[gid] = 0;
    int br = b >= GE0;
    const BP& bp = P.b[br];
    int e = (br ? b - GE0 : b) * 256 + tid;
    if (e < bp.E) {
        int d = bp.edges[bp.E + e];
        bp.eid[atomicAdd(bp.cursor + d, 1)] = e;
    }
}

// ============ K4/K8: block-per-node GCN gather (R3 body) ============
__global__ void k_gather(Pair P, int which) {
    __shared__ int ssrc[128];
    __shared__ float snorm[128];
    int task = blockIdx.x;
    int br = task >= P.b[0].N;
    const BP& bp = P.b[br];
    int d = br ? task - P.b[0].N : task;
    int j = threadIdx.x;
    const float* bias = which ? bp.gb2 : bp.gb1;
    float* out = which ? bp.f2 : bp.f1;
    const float* h = bp.h;
    float dd = bp.deg[d];
    float acc = fmaf(h[d * D + j], dd * dd, bias[j]);
    int rp = bp.rowptr[d], re = bp.rowptr[d + 1];
    for (int base = rp; base < re; base += 128) {
        int c = base + j;
        if (c < re) {
            int e = bp.eid[c];
            int s = bp.edges[e];
            ssrc[j] = s;
            snorm[j] = bp.deg[s] * bp.ew[e] * dd;
        }
        __syncthreads();
        int cnt = min(128, re - base);
        for (int t = 0; t < cnt; t++)
            acc = fmaf(h[ssrc[t] * D + j], snorm[t], acc);
        __syncthreads();
    }
    out[d * D + j] = fmaxf(acc, 0.f);
}

// ============ K5: GEMM2 (h2 = f1@aw) || attention dots ============
__global__ void k_gemm2attn(Pair P) {
    __shared__ float sA[2048];
    int tid = threadIdx.x;
    int b = blockIdx.x;
    if (b < G2) {
        int br = b >= GT0 * 8;
        int t = br ? b - GT0 * 8 : b;
        const BP& bp = P.b[br];
        gemm_tile(sA, tid, bp.f1, bp.aw, bp.h2, bp.N, HD, (t >> 3) << 4, (t & 7) << 7);
    } else {
        int task = (b - G2) * 8 + (tid >> 5);
        if (task < NT) {
            int br = task >= P.b[0].N;
            an_warp(P.b[br], br ? task - P.b[0].N : task, tid & 31);
        }
    }
}

// ============ K6: fused GAT, block-per-node (R3 body) ============
#define CH 128
__global__ void k_gat(Pair P) {
    __shared__ int ssrc[CH];
    __shared__ float sew[CH];
    __shared__ float scoef[8][CH];
    __shared__ float sm[8], sden[8], sc[8], sred[128];
    int task = blockIdx.x;
    int br = task >= P.b[0].N;
    const BP& bp = P.b[br];
    int d = br ? task - P.b[0].N : task;
    int tid = threadIdx.x, lane = tid & 31, wid = tid >> 5;
    if (tid < 8) sc[tid] = bp.cvec[tid];
    float meanw = bp.ewsum[0] / (float)bp.E;
    int rp = bp.rowptr[d];
    int deg = bp.rowptr[d + 1] - rp;
    int total = deg + 1;
    __syncthreads();
    float adst = bp.an_dst[d * H + wid];
    float chh = sc[wid];

    float m = -INFINITY, den = 0.f;
    for (int base = 0; base < total; base += CH) {
        int cnt = min(CH, total - base);
        if (tid < CH && base + tid < total) {
            int c = base + tid;
            if (c < deg) {
                int e = bp.eid[rp + c];
                ssrc[tid] = bp.edges[e];
                sew[tid] = bp.ew[e];
            } else { ssrc[tid] = d; sew[tid] = meanw; }
        }
        __syncthreads();
        float lg[4];
        int have = 0;
        float cm = -INFINITY;
        for (int c = lane; c < cnt; c += 32) {
            float l = bp.an_src[ssrc[c] * H + wid] + adst + sew[c] * chh;
            l = (l >= 0.f) ? l : 0.2f * l;
            lg[have++] = l;
            cm = fmaxf(cm, l);
        }
        #pragma unroll
        for (int o = 16; o; o >>= 1) cm = fmaxf(cm, __shfl_xor_sync(FULL, cm, o));
        float newm = fmaxf(m, cm);
        float ls = 0.f;
        for (int q = 0; q < have; q++) ls += __expf(lg[q] - newm);
        #pragma unroll
        for (int o = 16; o; o >>= 1) ls += __shfl_xor_sync(FULL, ls, o);
        den = den * __expf(m - newm) + ls;
        m = newm;
        __syncthreads();
    }
    if (lane == 0) { sm[wid] = m; sden[wid] = den + 1e-16f; }
    __syncthreads();

    int j = tid & 127;
    int hbase = (tid >> 7) * 4;
    float acc0 = 0.f, acc1 = 0.f, acc2 = 0.f, acc3 = 0.f;
    for (int base = 0; base < total; base += CH) {
        int cnt = min(CH, total - base);
        if (tid < CH && base + tid < total) {
            int c = base + tid;
            if (c < deg) {
                int e = bp.eid[rp + c];
                ssrc[tid] = bp.edges[e];
                sew[tid] = bp.ew[e];
            } else { ssrc[tid] = d; sew[tid] = meanw; }
        }
        __syncthreads();
        for (int c = lane; c < cnt; c += 32) {
            float l = bp.an_src[ssrc[c] * H + wid] + adst + sew[c] * chh;
            l = (l >= 0.f) ? l : 0.2f * l;
            scoef[wid][c] = __expf(l - sm[wid]) / sden[wid];
        }
        __syncthreads();
        for (int c = 0; c < cnt; c++) {
            const float* hr = bp.h2 + ssrc[c] * HD + hbase * D + j;
            acc0 = fmaf(hr[0],     scoef[hbase + 0][c], acc0);
            acc1 = fmaf(hr[D],     scoef[hbase + 1][c], acc1);
            acc2 = fmaf(hr[2 * D], scoef[hbase + 2][c], acc2);
            acc3 = fmaf(hr[3 * D], scoef[hbase + 3][c], acc3);
        }
        __syncthreads();
    }
    float part = acc0 + acc1 + acc2 + acc3;
    if (tid < 128) sred[j] = part;
    __syncthreads();
    if (tid >= 128)
        bp.att[d * D + j] = fmaxf(fmaf(sred[j] + part, 0.125f, bp.ab[j]), 0.f);
}

// ============ K7: GEMM3 (h = att@gw2) ============
__global__ void k_gemm3(Pair P) {
    __shared__ float sA[2048];
    int tid = threadIdx.x;
    int t = blockIdx.x;
    int br = t >= GT0;
    const BP& bp = P.b[br];
    gemm_tile(sA, tid, bp.att, bp.gw2, bp.h, bp.N, 128, (br ? t - GT0 : t) << 4, 0);
}

// ============ K9: CNN head (R3 body, flattened) ============
__global__ void k_cnn(Pair P) {
    __shared__ float sA[16 * 256];
    int b = blockIdx.x;                 // 0..GTILE*2-1
    int t = b >> 1, ch = b & 1;
    int br = t >= GT0;
    const BP& bp = P.b[br];
    int rb = (br ? t - GT0 : t) << 4;
    for (int idx = threadIdx.x; idx < 16 * 128; idx += 128) {
        int r = idx >> 7, k = idx & 127;
        int n = rb + r;
        sA[r * 256 + k] = (n < bp.N) ? bp.f1[n * D + k] : 0.f;
        sA[r * 256 + 128 + k] = (n < bp.N) ? bp.f2[n * D + k] : 0.f;
    }
    __syncthreads();
    int o = ch * 128 + threadIdx.x;
    float bo = bp.cb[o];
    float acc[16];
    #pragma unroll
    for (int r = 0; r < 16; r++) acc[r] = bo;
    const float* w = bp.cw + o * 256;
    #pragma unroll 8
    for (int k = 0; k < 256; k++) {
        float wv = w[k];
        #pragma unroll
        for (int r = 0; r < 16; r++) acc[r] = fmaf(sA[r * 256 + k], wv, acc[r]);
    }
    #pragma unroll
    for (int r = 0; r < 16; r++)
        if (rb + r < bp.N) bp.fea[(rb + r) * 256 + o] = acc[r];
}

// ============ K10: final matmul + state resets ============
__global__ void k_final(Pair P, float* __restrict__ out) {
    __shared__ float sA[16 * 256];
    int tid = threadIdx.x;
    int t = blockIdx.x;
    if (t >= GT0) {
        int idx = (t - GT0) * 128 + tid;
        if (idx < P.b[0].N) P.b[0].deg[idx] = 0.f;
        if (idx < P.b[1].N) P.b[1].deg[idx] = 0.f;
        if (idx == 0) { P.b[0].ewsum[0] = 0.f; P.b[1].ewsum[0] = 0.f; }
        return;
    }
    const float* cir = P.b[0].fea;
    const float* dis = P.b[1].fea;
    int ib = t * 16;
    for (int idx = tid; idx < 16 * 256; idx += 128) {
        int i = ib + (idx >> 8);
        sA[idx] = (i < NCIR) ? cir[i * 256 + (idx & 255)] : 0.f;
    }
    __syncthreads();
    int j = tid;
    if (j >= NDIS) return;
    float acc[16];
    #pragma unroll
    for (int r = 0; r < 16; r++) acc[r] = 0.f;
    const float* dr = dis + j * 256;
    #pragma unroll 8
    for (int k = 0; k < 256; k++) {
        float dv = dr[k];
        #pragma unroll
        for (int r = 0; r < 16; r++) acc[r] = fmaf(sA[r * 256 + k], dv, acc[r]);
    }
    #pragma unroll
    for (int r = 0; r < 16; r++)
        if (ib + r < NCIR) out[(ib + r) * NDIS + j] = acc[r];
}

// -------------------- host --------------------
static void fill_bp(BP& bp, const float* x, const float* mat, const int* edges,
                    const float* gw1, const float* gb1,
                    const float* aw, const float* asrc, const float* adst,
                    const float* aedge, const float* awe, const float* ab,
                    const float* gw2, const float* gb2,
                    const float* cw, const float* cb,
                    float* fea, int N, int E, float*& S) {
    bp.x = x; bp.mat = mat; bp.edges = edges;
    bp.gw1 = gw1; bp.gb1 = gb1; bp.aw = aw;
    bp.asrc = asrc; bp.adst = adst; bp.aedge = aedge;
    bp.awe = awe; bp.ab = ab; bp.gw2 = gw2; bp.gb2 = gb2;
    bp.cw = cw; bp.cb = cb;
    bp.fea = fea; bp.N = N; bp.E = E;
    bp.ew = S;        S += pad4(E);
    bp.deg = S;       S += pad4(N);
    bp.h = S;         S += pad4(N * D);
    bp.f1 = S;        S += pad4(N * D);
    bp.h2 = S;        S += pad4(N * HD);
    bp.an_src = S;    S += pad4(N * H);
    bp.an_dst = S;    S += pad4(N * H);
    bp.att = S;       S += pad4(N * D);
    bp.f2 = S;        S += pad4(N * D);
    bp.vsrc = S;      S += HD;
    bp.vdst = S;      S += HD;
    bp.cvec = S;      S += 8;
    bp.ewsum = S;     S += 8;
    bp.cnt = (int*)S;    S += pad4(N);
    bp.rowptr = (int*)S; S += pad4(N + 1);
    bp.cursor = (int*)S; S += pad4(N);
    bp.eid = (int*)S;    S += pad4(E);
}

extern "C" void kernel_launch(void* const* d_in, const int* in_sizes, int n_in,
                              void* d_out, int out_size) {
    float* S = nullptr;
    cudaGetSymbolAddress((void**)&S, g_scratch);

    const float* in_f[28];
    for (int i = 0; i < 28; i++) in_f[i] = (const float*)d_in[i];
    const int* cc_edges = (const int*)d_in[28];
    const int* dd_edges = (const int*)d_in[29];

    float* out = (float*)d_out;
    float* cirfea = out + NCIR * NDIS;
    float* disfea = cirfea + NCIR * 256;

    Pair P;
    float* cur = S;
    fill_bp(P.b[0], in_f[0], in_f[2], cc_edges,
            in_f[4], in_f[5], in_f[6], in_f[7], in_f[8], in_f[9], in_f[10], in_f[11],
            in_f[12], in_f[13], in_f[24], in_f[25], cirfea, NCIR, ECC, cur);
    fill_bp(P.b[1], in_f[1], in_f[3], dd_edges,
            in_f[14], in_f[15], in_f[16], in_f[17], in_f[18], in_f[19], in_f[20], in_f[21],
            in_f[22], in_f[23], in_f[26], in_f[27], disfea, NDIS, EDD, cur);

    k_phase1<<<GEDGE + GTILE + GPREP, 256>>>(P);
    k_scan<<<2, 256>>>(P);
    k_edge2<<<GEDGE, 256>>>(P);
    k_gather<<<NT, 128>>>(P, 0);
    k_gemm2attn<<<G2 + (NT + 7) / 8, 256>>>(P);
    k_gat<<<NT, 256>>>(P);
    k_gemm3<<<GTILE, 256>>>(P);
    k_gather<<<NT, 128>>>(P, 1);
    k_cnn<<<GTILE * 2, 128>>>(P);
    k_final<<<GT0 + 6, 128>>>(P, out);
}

// round 8
// speedup vs baseline: 1.8315x; 1.0904x over previous
#include <cuda_runtime.h>
#include <math.h>

#define D 128
#define HD 1024
#define H 8
#define NCIR 585
#define NDIS 88
#define ECC 20000
#define EDD 3000
#define BUCK 128            // max in-degree capacity (mean 34, sigma 5.8 -> safe)
#define GE0 79
#define GE1 12
#define GEDGE (GE0 + GE1)   // 91
#define GT0 37
#define GT1 6
#define GTILE (GT0 + GT1)   // 43
#define GPREP 86
#define NT (NCIR + NDIS)    // 673
#define G2 (GT0 * 8 + GT1 * 8)  // 344
#define FULL 0xffffffffu

__device__ __align__(16) float g_scratch[1300000];

struct BP {
    const float *x, *mat;
    const int *edges;
    const float *gb1, *ab, *gb2, *cw, *cb;
    const float *asrc, *adst, *aedge, *awe;
    const float *gw1, *aw, *gw2;
    float *fea;
    int N, E;
    float *degw, *h, *f1, *h2, *an_src, *an_dst, *att, *f2, *cvec, *ewsum;
    float *vsrc, *vdst, *eew;
    int *cnt, *esrc;
};
struct Pair { BP b[2]; };

static inline int pad4(int n) { return (n + 3) & ~3; }

__device__ __forceinline__ float4 ld4(const float* p) { return *(const float4*)p; }
__device__ __forceinline__ float wsum(float v) {
    #pragma unroll
    for (int o = 16; o; o >>= 1) v += __shfl_xor_sync(FULL, v, o);
    return v;
}

// ---- GEMM tile: C[rb:rb+16, cb:cb+128] = A[*,128] @ W[128,ncols], 256 thr ----
__device__ void gemm_tile(float* sA, int tid, const float* __restrict__ A,
                          const float* __restrict__ W, float* __restrict__ C,
                          int M, int ncols, int rb, int cb) {
    #pragma unroll
    for (int q = 0; q < 8; q++) {
        int idx = q * 256 + tid;
        int r = idx >> 7, k = idx & 127;
        sA[idx] = (rb + r < M) ? A[(rb + r) * 128 + k] : 0.f;
    }
    __syncthreads();
    int col = cb + (tid & 127);
    int r0 = (tid >> 7) << 3;
    float acc[8] = {0.f, 0.f, 0.f, 0.f, 0.f, 0.f, 0.f, 0.f};
    #pragma unroll 8
    for (int k = 0; k < 128; k++) {
        float w = W[k * ncols + col];
        #pragma unroll
        for (int r = 0; r < 8; r++) acc[r] = fmaf(sA[(r0 + r) * 128 + k], w, acc[r]);
    }
    #pragma unroll
    for (int r = 0; r < 8; r++)
        if (rb + r0 + r < M) C[(rb + r0 + r) * ncols + col] = acc[r];
}

// ---- va/cvec precompute (warp task) ----
__device__ void prep_warp(const Pair& P, int tt, int lane) {
    if (tt < 4096) {
        int br = tt >> 11; int r = tt & 2047;
        int type = r >> 10; r &= 1023;
        int hh = r >> 7; int k = r & 127;
        const BP& bp = P.b[br];
        const float* avec = type ? bp.adst : bp.asrc;
        float* vout = type ? bp.vdst : bp.vsrc;
        float4 w4 = ld4(bp.aw + k * HD + hh * D + lane * 4);
        float4 a4 = ld4(avec + hh * D + lane * 4);
        float s = wsum(w4.x * a4.x + w4.y * a4.y + w4.z * a4.z + w4.w * a4.w);
        if (lane == 0) vout[hh * D + k] = s;
    } else {
        int r = tt - 4096;
        if (r >= 16) return;
        int br = r >> 3; int hh = r & 7;
        const BP& bp = P.b[br];
        float4 a = ld4(bp.awe + hh * D + lane * 4);
        float4 e = ld4(bp.aedge + hh * D + lane * 4);
        float s = wsum(a.x * e.x + a.y * e.y + a.z * e.z + a.w * e.w);
        if (lane == 0) bp.cvec[hh] = s;
    }
}

// ---- attention node dots: an = f1 . va (warp task) ----
__device__ void an_warp(const BP& bp, int n, int lane) {
    float4 f = ld4(bp.f1 + n * D + lane * 4);
    #pragma unroll
    for (int hh = 0; hh < H; hh++) {
        float4 a = ld4(bp.vsrc + hh * D + lane * 4);
        float4 b = ld4(bp.vdst + hh * D + lane * 4);
        float s1 = wsum(f.x * a.x + f.y * a.y + f.z * a.z + f.w * a.w);
        float s2 = wsum(f.x * b.x + f.y * b.y + f.z * b.z + f.w * b.w);
        if (lane == 0) { bp.an_src[n * H + hh] = s1; bp.an_dst[n * H + hh] = s2; }
    }
}

// ============ K1: edge->buckets/deg/ewsum || GEMM1 || prep ============
__global__ void k_phase1(Pair P) {
    __shared__ float sA[2048];
    int tid = threadIdx.x, lane = tid & 31, wid = tid >> 5;
    int b = blockIdx.x;
    if (b < GEDGE) {
        int br = b >= GE0;
        const BP& bp = P.b[br];
        int e = (br ? b - GE0 : b) * 256 + tid;
        float w = 0.f;
        if (e < bp.E) {
            int s = bp.edges[e], d = bp.edges[bp.E + e];
            w = bp.mat[s * bp.N + d];
            int pos = atomicAdd(bp.cnt + d, 1);
            if (pos < BUCK) {
                bp.esrc[d * BUCK + pos] = s;
                bp.eew[d * BUCK + pos] = w;
            }
            atomicAdd(bp.degw + d, w);
        }
        float ws = w;
        #pragma unroll
        for (int o = 16; o; o >>= 1) ws += __shfl_down_sync(FULL, ws, o);
        if (lane == 0 && ws != 0.f) atomicAdd(bp.ewsum, ws);
    } else if (b < GEDGE + GTILE) {
        int t = b - GEDGE;
        int br = t >= GT0;
        const BP& bp = P.b[br];
        gemm_tile(sA, tid, bp.x, bp.gw1, bp.h, bp.N, 128, (br ? t - GT0 : t) << 4, 0);
    } else {
        int gw = (b - GEDGE - GTILE) * 8 + wid;
        for (int tt = gw; tt < 4112; tt += GPREP * 8) prep_warp(P, tt, lane);
    }
}

// ============ K2/K6: block-per-node GCN gather (bucket, single chunk) ============
__global__ void k_gather(Pair P, int which) {
    __shared__ int ssrc[BUCK];
    __shared__ float snorm[BUCK];
    int task = blockIdx.x;
    int br = task >= P.b[0].N;
    const BP& bp = P.b[br];
    int d = br ? task - P.b[0].N : task;
    int j = threadIdx.x;
    const float* bias = which ? bp.gb2 : bp.gb1;
    float* out = which ? bp.f2 : bp.f1;
    const float* h = bp.h;
    float dd = rsqrtf(bp.degw[d] + 1.0f);
    int deg = min(bp.cnt[d], BUCK);
    if (j < deg) {
        int s = bp.esrc[d * BUCK + j];
        ssrc[j] = s;
        snorm[j] = rsqrtf(bp.degw[s] + 1.0f) * bp.eew[d * BUCK + j] * dd;
    }
    __syncthreads();
    float acc = fmaf(h[d * D + j], dd * dd, bias[j]);
    #pragma unroll 4
    for (int t = 0; t < deg; t++)
        acc = fmaf(h[ssrc[t] * D + j], snorm[t], acc);
    out[d * D + j] = fmaxf(acc, 0.f);
}

// ============ K3: GEMM2 (h2 = f1@aw) || attention dots ============
__global__ void k_gemm2attn(Pair P) {
    __shared__ float sA[2048];
    int tid = threadIdx.x;
    int b = blockIdx.x;
    if (b < G2) {
        int br = b >= GT0 * 8;
        int t = br ? b - GT0 * 8 : b;
        const BP& bp = P.b[br];
        gemm_tile(sA, tid, bp.f1, bp.aw, bp.h2, bp.N, HD, (t >> 3) << 4, (t & 7) << 7);
    } else {
        int task = (b - G2) * 8 + (tid >> 5);
        if (task < NT) {
            int br = task >= P.b[0].N;
            an_warp(P.b[br], br ? task - P.b[0].N : task, tid & 31);
        }
    }
}

// ============ K4: fused GAT, block-per-node, single-shot (total <= BUCK+1) ============
#define GCH (BUCK + 8)
__global__ void k_gat(Pair P) {
    __shared__ int ssrc[GCH];
    __shared__ float sew[GCH];
    __shared__ float scoef[8][GCH];
    __shared__ float sc[8], sred[128];
    int task = blockIdx.x;
    int br = task >= P.b[0].N;
    const BP& bp = P.b[br];
    int d = br ? task - P.b[0].N : task;
    int tid = threadIdx.x, lane = tid & 31, wid = tid >> 5;
    if (tid < 8) sc[tid] = bp.cvec[tid];
    float meanw = bp.ewsum[0] / (float)bp.E;
    int deg = min(bp.cnt[d], BUCK);
    int total = deg + 1;
    // load neighbor list + self loop (single shot: total <= 129 <= 256 threads)
    if (tid < total) {
        if (tid < deg) {
            ssrc[tid] = bp.esrc[d * BUCK + tid];
            sew[tid] = bp.eew[d * BUCK + tid];
        } else { ssrc[tid] = d; sew[tid] = meanw; }
    }
    __syncthreads();
    float adst = bp.an_dst[d * H + wid];
    float chh = sc[wid];

    // logits once into smem, then max/den, then normalize in place (warp wid = head)
    float m = -INFINITY;
    for (int c = lane; c < total; c += 32) {
        float l = bp.an_src[ssrc[c] * H + wid] + adst + sew[c] * chh;
        l = (l >= 0.f) ? l : 0.2f * l;
        scoef[wid][c] = l;
        m = fmaxf(m, l);
    }
    #pragma unroll
    for (int o = 16; o; o >>= 1) m = fmaxf(m, __shfl_xor_sync(FULL, m, o));
    float den = 0.f;
    for (int c = lane; c < total; c += 32) den += __expf(scoef[wid][c] - m);
    #pragma unroll
    for (int o = 16; o; o >>= 1) den += __shfl_xor_sync(FULL, den, o);
    float inv = 1.f / (den + 1e-16f);
    for (int c = lane; c < total; c += 32)
        scoef[wid][c] = __expf(scoef[wid][c] - m) * inv;
    __syncthreads();

    // aggregation: thread (half,j) covers heads half*4..+3, column j
    int j = tid & 127;
    int hbase = (tid >> 7) * 4;
    float acc0 = 0.f, acc1 = 0.f, acc2 = 0.f, acc3 = 0.f;
    for (int c = 0; c < total; c++) {
        const float* hr = bp.h2 + ssrc[c] * HD + hbase * D + j;
        acc0 = fmaf(hr[0],     scoef[hbase + 0][c], acc0);
        acc1 = fmaf(hr[D],     scoef[hbase + 1][c], acc1);
        acc2 = fmaf(hr[2 * D], scoef[hbase + 2][c], acc2);
        acc3 = fmaf(hr[3 * D], scoef[hbase + 3][c], acc3);
    }
    float part = acc0 + acc1 + acc2 + acc3;
    if (tid < 128) sred[j] = part;
    __syncthreads();
    if (tid >= 128)
        bp.att[d * D + j] = fmaxf(fmaf(sred[j] + part, 0.125f, bp.ab[j]), 0.f);
}

// ============ K5: GEMM3 (h = att@gw2) ============
__global__ void k_gemm3(Pair P) {
    __shared__ float sA[2048];
    int tid = threadIdx.x;
    int t = blockIdx.x;
    int br = t >= GT0;
    const BP& bp = P.b[br];
    gemm_tile(sA, tid, bp.att, bp.gw2, bp.h, bp.N, 128, (br ? t - GT0 : t) << 4, 0);
}

// ============ K7: CNN head ============
__global__ void k_cnn(Pair P) {
    __shared__ float sA[16 * 256];
    int b = blockIdx.x;
    int t = b >> 1, ch = b & 1;
    int br = t >= GT0;
    const BP& bp = P.b[br];
    int rb = (br ? t - GT0 : t) << 4;
    for (int idx = threadIdx.x; idx < 16 * 128; idx += 128) {
        int r = idx >> 7, k = idx & 127;
        int n = rb + r;
        sA[r * 256 + k] = (n < bp.N) ? bp.f1[n * D + k] : 0.f;
        sA[r * 256 + 128 + k] = (n < bp.N) ? bp.f2[n * D + k] : 0.f;
    }
    __syncthreads();
    int o = ch * 128 + threadIdx.x;
    float bo = bp.cb[o];
    float acc[16];
    #pragma unroll
    for (int r = 0; r < 16; r++) acc[r] = bo;
    const float* w = bp.cw + o * 256;
    #pragma unroll 8
    for (int k = 0; k < 256; k++) {
        float wv = w[k];
        #pragma unroll
        for (int r = 0; r < 16; r++) acc[r] = fmaf(sA[r * 256 + k], wv, acc[r]);
    }
    #pragma unroll
    for (int r = 0; r < 16; r++)
        if (rb + r < bp.N) bp.fea[(rb + r) * 256 + o] = acc[r];
}

// ============ K8: final matmul + state resets ============
__global__ void k_final(Pair P, float* __restrict__ out) {
    __shared__ float sA[16 * 256];
    int tid = threadIdx.x;
    int t = blockIdx.x;
    if (t >= GT0) {
        int idx = (t - GT0) * 128 + tid;
        if (idx < P.b[0].N) { P.b[0].degw[idx] = 0.f; P.b[0].cnt[idx] = 0; }
        if (idx < P.b[1].N) { P.b[1].degw[idx] = 0.f; P.b[1].cnt[idx] = 0; }
        if (idx == 0) { P.b[0].ewsum[0] = 0.f; P.b[1].ewsum[0] = 0.f; }
        return;
    }
    const float* cir = P.b[0].fea;
    const float* dis = P.b[1].fea;
    int ib = t * 16;
    for (int idx = tid; idx < 16 * 256; idx += 128) {
        int i = ib + (idx >> 8);
        sA[idx] = (i < NCIR) ? cir[i * 256 + (idx & 255)] : 0.f;
    }
    __syncthreads();
    int j = tid;
    if (j >= NDIS) return;
    float acc[16];
    #pragma unroll
    for (int r = 0; r < 16; r++) acc[r] = 0.f;
    const float* dr = dis + j * 256;
    #pragma unroll 8
    for (int k = 0; k < 256; k++) {
        float dv = dr[k];
        #pragma unroll
        for (int r = 0; r < 16; r++) acc[r] = fmaf(sA[r * 256 + k], dv, acc[r]);
    }
    #pragma unroll
    for (int r = 0; r < 16; r++)
        if (ib + r < NCIR) out[(ib + r) * NDIS + j] = acc[r];
}

// -------------------- host --------------------
static void fill_bp(BP& bp, const float* x, const float* mat, const int* edges,
                    const float* gw1, const float* gb1,
                    const float* aw, const float* asrc, const float* adst,
                    const float* aedge, const float* awe, const float* ab,
                    const float* gw2, const float* gb2,
                    const float* cw, const float* cb,
                    float* fea, int N, int E, float*& S) {
    bp.x = x; bp.mat = mat; bp.edges = edges;
    bp.gw1 = gw1; bp.gb1 = gb1; bp.aw = aw;
    bp.asrc = asrc; bp.adst = adst; bp.aedge = aedge;
    bp.awe = awe; bp.ab = ab; bp.gw2 = gw2; bp.gb2 = gb2;
    bp.cw = cw; bp.cb = cb;
    bp.fea = fea; bp.N = N; bp.E = E;
    bp.degw = S;      S += pad4(N);
    bp.h = S;         S += pad4(N * D);
    bp.f1 = S;        S += pad4(N * D);
    bp.h2 = S;        S += pad4(N * HD);
    bp.an_src = S;    S += pad4(N * H);
    bp.an_dst = S;    S += pad4(N * H);
    bp.att = S;       S += pad4(N * D);
    bp.f2 = S;        S += pad4(N * D);
    bp.vsrc = S;      S += HD;
    bp.vdst = S;      S += HD;
    bp.cvec = S;      S += 8;
    bp.ewsum = S;     S += 8;
    bp.eew = S;       S += pad4(N * BUCK);
    bp.cnt = (int*)S;    S += pad4(N);
    bp.esrc = (int*)S;   S += pad4(N * BUCK);
}

extern "C" void kernel_launch(void* const* d_in, const int* in_sizes, int n_in,
                              void* d_out, int out_size) {
    float* S = nullptr;
    cudaGetSymbolAddress((void**)&S, g_scratch);

    const float* in_f[28];
    for (int i = 0; i < 28; i++) in_f[i] = (const float*)d_in[i];
    const int* cc_edges = (const int*)d_in[28];
    const int* dd_edges = (const int*)d_in[29];

    float* out = (float*)d_out;
    float* cirfea = out + NCIR * NDIS;
    float* disfea = cirfea + NCIR * 256;

    Pair P;
    float* cur = S;
    fill_bp(P.b[0], in_f[0], in_f[2], cc_edges,
            in_f[4], in_f[5], in_f[6], in_f[7], in_f[8], in_f[9], in_f[10], in_f[11],
            in_f[12], in_f[13], in_f[24], in_f[25], cirfea, NCIR, ECC, cur);
    fill_bp(P.b[1], in_f[1], in_f[3], dd_edges,
            in_f[14], in_f[15], in_f[16], in_f[17], in_f[18], in_f[19], in_f[20], in_f[21],
            in_f[22], in_f[23], in_f[26], in_f[27], disfea, NDIS, EDD, cur);

    k_phase1<<<GEDGE + GTILE + GPREP, 256>>>(P);
    k_gather<<<NT, 128>>>(P, 0);
    k_gemm2attn<<<G2 + (NT + 7) / 8, 256>>>(P);
    k_gat<<<NT, 256>>>(P);
    k_gemm3<<<GTILE, 256>>>(P);
    k_gather<<<NT, 128>>>(P, 1);
    k_cnn<<<GTILE * 2, 128>>>(P);
    k_final<<<GT0 + 6, 128>>>(P, out);
}